// round 4
// baseline (speedup 1.0000x reference)
#include <cuda_runtime.h>
#include <cuda_bf16.h>
#include <cstdint>
#include <cfloat>

// Problem constants (fixed by the reference)
#define NW        4
#define CCH       32
#define MPW       8
#define IMG_H     1024
#define IMG_W     1024
#define HW        (IMG_H * IMG_W)
#define WIN_H     512
#define WIN_W     512
#define SLOT_DIM  64
#define SIM_THRESH 0.1f
#define P_MAX     304

#define CHUNK     2048       // pixels per block in main kernel
#define PPT       8          // pixels per thread (CHUNK/256)
#define NSTAGE    8          // cp.async ring depth

// Scratch (device globals; no runtime allocation allowed)
__device__ unsigned d_edge_sub[16][64];   // [window*4+edge][sub-block] bitmasks
__device__ int      d_map[CCH];

__device__ __forceinline__ uint32_t smem_u32(const void* p) {
    return (uint32_t)__cvta_generic_to_shared(p);
}

// ---------------------------------------------------------------------------
// K1: edge flags, channels-in-lanes. One warp per edge pixel; lane = channel.
// 8192 pixel slots -> 1024 blocks x 8 warps. Each block writes its own sub
// word unconditionally -> no init kernel, no atomics.
// ---------------------------------------------------------------------------
__global__ void __launch_bounds__(256) edge_kernel(
    const float* __restrict__ masks,
    const int* __restrict__ pad_left,
    const int* __restrict__ pad_top)
{
    const int warp = threadIdx.x >> 5;
    const int lane = threadIdx.x & 31;
    const int gp = blockIdx.x * 8 + warp;   // global pixel slot
    const int ei = gp >> 9;                 // window*4+edge (0..15)
    const int k  = gp & 511;                // pixel along edge
    const int w  = ei >> 2;
    const int e  = ei & 3;                  // 0=L 1=R 2=T 3=B

    int pl = pad_left[w], pt = pad_top[w];
    int ys = max(pt, 0), ye = min(pt + WIN_H, IMG_H);
    int xs = max(pl, 0), xe = min(pl + WIN_W, IMG_W);

    unsigned bit = 0u;
    if (ys < ye && xs < xe) {
        int len = (e < 2) ? (ye - ys) : (xe - xs);
        if (k < len) {                       // warp-uniform predicate
            int y, x;
            if      (e == 0) { y = ys + k; x = xs;     }
            else if (e == 1) { y = ys + k; x = xe - 1; }
            else if (e == 2) { y = ys;     x = xs + k; }
            else             { y = ye - 1; x = xs + k; }
            float v = __ldg(masks + (size_t)lane * HW + (size_t)y * IMG_W + x);
            int id = lane;
            #pragma unroll
            for (int off = 16; off > 0; off >>= 1) {
                float v2 = __shfl_down_sync(0xffffffffu, v, off);
                int   i2 = __shfl_down_sync(0xffffffffu, id, off);
                if (v2 > v || (v2 == v && i2 < id)) { v = v2; id = i2; }
            }
            if (lane == 0 && (id >> 3) == w) bit = 1u << id;
        }
    }

    __shared__ unsigned sb[8];
    if (lane == 0) sb[warp] = bit;
    __syncthreads();
    if (threadIdx.x == 0) {
        unsigned a = 0;
        #pragma unroll
        for (int i = 0; i < 8; i++) a |= sb[i];
        d_edge_sub[ei][blockIdx.x & 63] = a;
    }
}

// ---------------------------------------------------------------------------
// K2: one block. Reduce edge bitmasks, build adjacency + candidate pairs,
// cosine sims, sequential merge scan -> 32-entry channel remap table.
// ---------------------------------------------------------------------------
__global__ void __launch_bounds__(256) map_kernel(
    const float* __restrict__ sf,
    const int* __restrict__ pad_left,
    const int* __restrict__ pad_top)
{
    __shared__ int  s_ci[P_MAX];
    __shared__ int  s_cj[P_MAX];
    __shared__ char s_hz[P_MAX];
    __shared__ char s_pass[P_MAX];
    __shared__ int  s_P;
    __shared__ unsigned s_edge[NW][4];

    if (threadIdx.x < 16) {
        unsigned a = 0;
        for (int i = 0; i < 64; i++) a |= d_edge_sub[threadIdx.x][i];
        s_edge[threadIdx.x >> 2][threadIdx.x & 3] = a;
    }

    if (threadIdx.x == 0) {
        int pl[NW], pt[NW];
        for (int i = 0; i < NW; i++) { pl[i] = pad_left[i]; pt[i] = pad_top[i]; }

        int na = 0;
        int ai[12], aj[12]; char ah[12];
        for (int i = 0; i < NW; i++) {
            for (int j = i + 1; j < NW; j++) {
                if (pt[i] == pt[j] && abs(pl[i] - pl[j]) == WIN_W) {
                    if (pl[i] < pl[j]) { ai[na] = i; aj[na] = j; }
                    else               { ai[na] = j; aj[na] = i; }
                    ah[na] = 1; na++;
                }
                if (pl[i] == pl[j] && abs(pt[i] - pt[j]) == WIN_H) {
                    if (pt[i] < pt[j]) { ai[na] = i; aj[na] = j; }
                    else               { ai[na] = j; aj[na] = i; }
                    ah[na] = 0; na++;
                }
            }
        }
        int P = 0;
        for (int a = 0; a < na; a++) {
            int si = ai[a] * MPW, sj = aj[a] * MPW;
            for (int ci = si + 1; ci < si + MPW; ci++)
                for (int cj = sj + 1; cj < sj + MPW; cj++) {
                    s_ci[P] = ci; s_cj[P] = cj; s_hz[P] = ah[a]; P++;
                }
        }
        s_P = P;
    }
    __syncthreads();

    int P = s_P;
    for (int p = threadIdx.x; p < P; p += blockDim.x) {
        int ci = s_ci[p], cj = s_cj[p];
        int wi = ci / MPW, wj = cj / MPW;
        int ri = ci % MPW - 1, rj = cj % MPW - 1;
        const float* fi = sf + ((long long)wi * (MPW - 1) + ri) * SLOT_DIM;
        const float* fj = sf + ((long long)wj * (MPW - 1) + rj) * SLOT_DIM;
        float dot = 0.f, ni = 0.f, nj = 0.f;
        #pragma unroll
        for (int k = 0; k < SLOT_DIM; k++) {
            float a = fi[k], b = fj[k];
            dot += a * b; ni += a * a; nj += b * b;
        }
        float sim = dot / ((sqrtf(ni) + 1e-8f) * (sqrtf(nj) + 1e-8f));

        bool ok;
        if (s_hz[p]) {
            ok = ((s_edge[wi][1] >> ci) & 1u) && ((s_edge[wj][0] >> cj) & 1u);
        } else {
            ok = ((s_edge[wi][3] >> ci) & 1u) && ((s_edge[wj][2] >> cj) & 1u);
        }
        s_pass[p] = (ok && sim > SIM_THRESH) ? 1 : 0;
    }
    __syncthreads();

    if (threadIdx.x == 0) {
        int mp[CCH];
        bool merged[CCH];
        for (int c = 0; c < CCH; c++) { mp[c] = c; merged[c] = false; }
        for (int p = 0; p < P; p++) {
            int ci = s_ci[p], cj = s_cj[p];
            if (s_pass[p] && !merged[ci] && !merged[cj]) {
                int keep = min(ci, cj), rem = max(ci, cj);
                for (int c = 0; c < CCH; c++)
                    if (mp[c] == rem) mp[c] = keep;
                merged[rem] = true;
            }
        }
        for (int c = 0; c < CCH; c++) d_map[c] = mp[c];
    }
}

// ---------------------------------------------------------------------------
// K3: fused main pass. Reads pipelined via 8-stage cp.async ring (8KB per
// channel per block, purely per-thread ownership -> no barriers in read loop),
// per-pixel argmax + remap, then per-channel SMEM staging + cp.async.bulk
// stores (double-buffered).
// ---------------------------------------------------------------------------
__global__ void __launch_bounds__(256) main_kernel(
    const float* __restrict__ masks,
    float* __restrict__ out)
{
    extern __shared__ __align__(16) float dsm[];
    float* sin  = dsm;                    // NSTAGE * CHUNK floats (64KB)
    float* sout = dsm + NSTAGE * CHUNK;   // 2 * CHUNK floats (16KB)

    __shared__ int smap[CCH];
    const int t = threadIdx.x;
    if (t < CCH) smap[t] = d_map[t];
    __syncthreads();

    const size_t base = (size_t)blockIdx.x * CHUNK;   // pixel index of chunk

    // prologue: issue first NSTAGE channels
    #pragma unroll
    for (int c = 0; c < NSTAGE; c++) {
        const float* src = masks + (size_t)c * HW + base + t * PPT;
        uint32_t d = smem_u32(sin + c * CHUNK + t * PPT);
        asm volatile(
            "cp.async.cg.shared.global [%0], [%1], 16;\n\t"
            "cp.async.cg.shared.global [%2], [%3], 16;\n\t"
            "cp.async.commit_group;"
            :: "r"(d), "l"(src), "r"(d + 16), "l"(src + 4) : "memory");
    }

    float best[PPT];
    int   ida[PPT];
    #pragma unroll
    for (int i = 0; i < PPT; i++) { best[i] = -INFINITY; ida[i] = 0; }

    for (int c = 0; c < CCH; c++) {
        asm volatile("cp.async.wait_group %0;" :: "n"(NSTAGE - 1));
        const float4* p = (const float4*)(sin + (c & (NSTAGE - 1)) * CHUNK + t * PPT);
        float4 a = p[0], b = p[1];
        float v[PPT] = {a.x, a.y, a.z, a.w, b.x, b.y, b.z, b.w};
        #pragma unroll
        for (int i = 0; i < PPT; i++)
            if (v[i] > best[i]) { best[i] = v[i]; ida[i] = c; }

        int cn = c + NSTAGE;
        if (cn < CCH) {
            const float* src = masks + (size_t)cn * HW + base + t * PPT;
            uint32_t d = smem_u32(sin + (cn & (NSTAGE - 1)) * CHUNK + t * PPT);
            asm volatile(
                "cp.async.cg.shared.global [%0], [%1], 16;\n\t"
                "cp.async.cg.shared.global [%2], [%3], 16;\n\t"
                "cp.async.commit_group;"
                :: "r"(d), "l"(src), "r"(d + 16), "l"(src + 4) : "memory");
        } else {
            asm volatile("cp.async.commit_group;" ::: "memory");
        }
    }

    #pragma unroll
    for (int i = 0; i < PPT; i++) ida[i] = smap[ida[i]];

    // staged one-hot writes, double buffered bulk stores
    for (int c = 0; c < CCH; c++) {
        int buf = c & 1;
        if (c >= 2) {
            if (t == 0)
                asm volatile("cp.async.bulk.wait_group.read 1;" ::: "memory");
            __syncthreads();
        }
        float4* sb4 = (float4*)(sout + buf * CHUNK + t * PPT);
        float4 o1, o2;
        o1.x = (ida[0] == c) ? 1.0f : 0.0f;
        o1.y = (ida[1] == c) ? 1.0f : 0.0f;
        o1.z = (ida[2] == c) ? 1.0f : 0.0f;
        o1.w = (ida[3] == c) ? 1.0f : 0.0f;
        o2.x = (ida[4] == c) ? 1.0f : 0.0f;
        o2.y = (ida[5] == c) ? 1.0f : 0.0f;
        o2.z = (ida[6] == c) ? 1.0f : 0.0f;
        o2.w = (ida[7] == c) ? 1.0f : 0.0f;
        sb4[0] = o1; sb4[1] = o2;
        __syncthreads();
        if (t == 0) {
            float* gdst = out + (size_t)c * HW + base;
            uint32_t saddr = smem_u32(sout + buf * CHUNK);
            asm volatile("fence.proxy.async.shared::cta;" ::: "memory");
            asm volatile(
                "cp.async.bulk.global.shared::cta.bulk_group [%0], [%1], %2;"
                :: "l"(gdst), "r"(saddr), "n"(CHUNK * 4) : "memory");
            asm volatile("cp.async.bulk.commit_group;" ::: "memory");
        }
    }
    if (t == 0)
        asm volatile("cp.async.bulk.wait_group.read 0;" ::: "memory");
    __syncthreads();
}

// ---------------------------------------------------------------------------
extern "C" void kernel_launch(void* const* d_in, const int* in_sizes, int n_in,
                              void* d_out, int out_size)
{
    const float* masks = (const float*)d_in[0];
    const float* sf    = (const float*)d_in[1];
    const int*   pl    = (const int*)d_in[2];
    const int*   pt    = (const int*)d_in[3];
    float*       out   = (float*)d_out;

    static bool configured = false;
    if (!configured) {
        cudaFuncSetAttribute(main_kernel,
                             cudaFuncAttributeMaxDynamicSharedMemorySize,
                             (NSTAGE + 2) * CHUNK * 4);
        configured = true;
    }

    edge_kernel<<<1024, 256>>>(masks, pl, pt);
    map_kernel<<<1, 256>>>(sf, pl, pt);
    main_kernel<<<HW / CHUNK, 256, (NSTAGE + 2) * CHUNK * 4>>>(masks, out);
}